// round 14
// baseline (speedup 1.0000x reference)
#include <cuda_runtime.h>
#include <cuda_bf16.h>
#include <cuda_fp16.h>
#include <cstdint>

#define BB 2
#define HH 16
#define LLEN 1024
#define RREL 16

// ---------------- helpers ----------------
__device__ __forceinline__ uint32_t smem_u32(const void* p) {
    uint32_t a;
    asm("{ .reg .u64 t; cvta.to.shared.u64 t, %1; cvt.u32.u64 %0, t; }" : "=r"(a) : "l"(p));
    return a;
}
#define SWZ(off) ((off) ^ (((off) >> 3) & 0x70))

__device__ __forceinline__ void ldmx4(uint32_t* r, uint32_t addr) {
    asm volatile("ldmatrix.sync.aligned.m8n8.x4.shared.b16 {%0,%1,%2,%3}, [%4];"
                 : "=r"(r[0]), "=r"(r[1]), "=r"(r[2]), "=r"(r[3]) : "r"(addr));
}
__device__ __forceinline__ void mma16816h(float* c, const uint32_t* a,
                                          uint32_t b0, uint32_t b1) {
    asm volatile(
        "mma.sync.aligned.m16n8k16.row.col.f32.f16.f16.f32 "
        "{%0,%1,%2,%3}, {%4,%5,%6,%7}, {%8,%9}, {%0,%1,%2,%3};"
        : "+f"(c[0]), "+f"(c[1]), "+f"(c[2]), "+f"(c[3])
        : "r"(a[0]), "r"(a[1]), "r"(a[2]), "r"(a[3]), "r"(b0), "r"(b1));
}
__device__ __forceinline__ unsigned bf2pack(float x, float y) {
    __nv_bfloat162 h = __float22bfloat162_rn(make_float2(x, y));
    return *(unsigned*)&h;
}
__device__ __forceinline__ unsigned h2pack(float x, float y) {
    __half2 h = __floats2half2_rn(x, y);
    return *(unsigned*)&h;
}

// ---------------- fused kernel ----------------
// smem layout (99456 B dynamic):
//   us  bf16[128][UVS=68] @ 0       (17408)
//   v_t bf16[16][VST=516] @ 17408   (16512)
//   @33920 (SM_TB): QHI(16K) QLO(16K) KHI(16K) As1(8K fp16) As2(8K fp16)  [GEMM phase]
//   D_s fp32[128][128] slot-swizzled @ SM_TB (64K, exactly aliases tiles+As) [epilogue]
#define UVS 68
#define VST 516
#define SM_VT 17408
#define SM_TB 33920
#define SM_QHI (SM_TB + 0)
#define SM_QLO (SM_TB + 16384)
#define SM_KHI (SM_TB + 32768)
#define SM_AS1 (SM_TB + 49152)
#define SM_AS2 (SM_TB + 57344)
#define DYN_SMEM (SM_TB + 65536)

__global__ __launch_bounds__(256, 2) void relmat_fused(
    const float* __restrict__ Q, const float* __restrict__ K,
    const int* __restrict__ ids, const float* __restrict__ A1,
    const float* __restrict__ A2, float* __restrict__ out)
{
    extern __shared__ char sm8[];
    uint32_t sb = smem_u32(sm8);
    __nv_bfloat16* us_h = (__nv_bfloat16*)(sm8);
    __nv_bfloat16* vs_t = (__nv_bfloat16*)(sm8 + SM_VT);
    float* D_s = (float*)(sm8 + SM_TB);

    int bh = blockIdx.z, b = bh >> 4, h = bh & 15;
    int l0 = blockIdx.y * 128, m0 = blockIdx.x * 128;
    int tid = threadIdx.x, lane = tid & 31, warp = tid >> 5;
    int warp_m = warp & 3, warp_n = warp >> 2;   // 4x2 warp grid, warp tile 32x64

    // ---- phase 0: stage A1/A2 head slices as fp16 [oc][d] swizzled ----
    for (int t = tid; t < 4096; t += 256) {
        int r = t >> 8, rem = t & 255;
        float a1 = A1[(size_t)(r * HH + h) * 256 + rem];
        int oc1 = r * 4 + (rem & 3), d1 = rem >> 2;
        *(__half*)(sm8 + SM_AS1 + SWZ((uint32_t)(oc1 * 128 + d1 * 2))) = __float2half(a1);
        float a2 = A2[(size_t)(r * HH + h) * 256 + rem];
        int oc2 = r * 4 + (rem >> 6), d2 = rem & 63;
        *(__half*)(sm8 + SM_AS2 + SWZ((uint32_t)(oc2 * 128 + d2 * 2))) = __float2half(a2);
    }

    // ---- phase 1: load Q (fp16 hi+lo) and K (fp16 hi), swizzled ----
    const float* Qb = Q + ((size_t)bh * LLEN + l0) * 64;
    const float* Kb = K + ((size_t)bh * LLEN + m0) * 64;
#pragma unroll
    for (int it = 0; it < 8; it++) {
        int idx = tid + 256 * it;
        int row = idx >> 4, c4 = idx & 15;
        uint32_t off = SWZ((uint32_t)(row * 128 + c4 * 8));
        {
            float4 v = *(const float4*)(Qb + (size_t)row * 64 + c4 * 4);
            __half2 h0 = __floats2half2_rn(v.x, v.y);
            __half2 h1 = __floats2half2_rn(v.z, v.w);
            float2 r0 = make_float2(v.x - __half2float(__low2half(h0)),
                                    v.y - __half2float(__high2half(h0)));
            float2 r1 = make_float2(v.z - __half2float(__low2half(h1)),
                                    v.w - __half2float(__high2half(h1)));
            *(uint2*)(sm8 + SM_QHI + off) = make_uint2(*(unsigned*)&h0, *(unsigned*)&h1);
            *(uint2*)(sm8 + SM_QLO + off) = make_uint2(h2pack(r0.x, r0.y), h2pack(r1.x, r1.y));
        }
        {
            float4 v = *(const float4*)(Kb + (size_t)row * 64 + c4 * 4);
            *(uint2*)(sm8 + SM_KHI + off) = make_uint2(h2pack(v.x, v.y), h2pack(v.z, v.w));
        }
    }
    __syncthreads();

    // ---- phase 2: in-CTA u = QHI@A1, v = KHI@A2 (fp16 mma, bf16 out to smem) ----
    {
        int lrA = warp * 16 + (lane & 15);
        int lrB = (lane & 15);
        int kb = lane >> 4;
        int r0 = warp * 16 + (lane >> 2), c0 = 2 * (lane & 3);
#pragma unroll
        for (int uv = 0; uv < 2; uv++) {
            uint32_t base = sb + (uv ? SM_KHI : SM_QHI);
            uint32_t abase = sb + (uv ? SM_AS2 : SM_AS1);
            float Cu[8][4];
#pragma unroll
            for (int nt = 0; nt < 8; nt++)
#pragma unroll
                for (int q = 0; q < 4; q++) Cu[nt][q] = 0.f;
#pragma unroll
            for (int ks = 0; ks < 4; ks++) {
                uint32_t kcol = (uint32_t)((ks * 2 + kb) * 16);
                uint32_t af[4];
                ldmx4(af, base + SWZ((uint32_t)(lrA * 128) + kcol));
#pragma unroll
                for (int ntp = 0; ntp < 4; ntp++) {
                    uint32_t bfr[4];
                    ldmx4(bfr, abase + SWZ((uint32_t)((lrB + ntp * 16) * 128) + kcol));
                    mma16816h(Cu[ntp * 2],     af, bfr[0], bfr[2]);
                    mma16816h(Cu[ntp * 2 + 1], af, bfr[1], bfr[3]);
                }
            }
            if (uv == 0) {
#pragma unroll
                for (int nt = 0; nt < 8; nt++) {
                    *(unsigned*)&us_h[r0 * UVS + nt * 8 + c0] = bf2pack(Cu[nt][0], Cu[nt][1]);
                    *(unsigned*)&us_h[(r0 + 8) * UVS + nt * 8 + c0] = bf2pack(Cu[nt][2], Cu[nt][3]);
                }
            } else {
#pragma unroll
                for (int nt = 0; nt < 8; nt++) {
                    int oc = nt * 8 + c0;
                    int rc = oc >> 2, e = oc & 3;
                    *(unsigned*)&vs_t[rc * VST + r0 * 4 + e] = bf2pack(Cu[nt][0], Cu[nt][1]);
                    *(unsigned*)&vs_t[rc * VST + (r0 + 8) * 4 + e] = bf2pack(Cu[nt][2], Cu[nt][3]);
                }
            }
        }
    }

    // ---- phase 3: main GEMM, 2 fp16 passes fused per k-step ----
    float C[2][8][4];
#pragma unroll
    for (int mt = 0; mt < 2; mt++)
#pragma unroll
        for (int nt = 0; nt < 8; nt++)
#pragma unroll
            for (int q = 0; q < 4; q++) C[mt][nt][q] = 0.f;

    int lrowA = warp_m * 32 + (lane & 15);
    int lrowB = warp_n * 64 + (lane & 15);
    int kb = (lane >> 4);

#pragma unroll
    for (int ks = 0; ks < 4; ks++) {
        uint32_t kcol = (uint32_t)((ks * 2 + kb) * 16);
        uint32_t ah[2][4], al[2][4];
#pragma unroll
        for (int mt = 0; mt < 2; mt++) {
            uint32_t aoff = SWZ((uint32_t)((lrowA + mt * 16) * 128) + kcol);
            ldmx4(ah[mt], sb + SM_QHI + aoff);
            ldmx4(al[mt], sb + SM_QLO + aoff);
        }
#pragma unroll
        for (int ntp = 0; ntp < 4; ntp++) {
            uint32_t boff = SWZ((uint32_t)((lrowB + ntp * 16) * 128) + kcol);
            uint32_t bhf[4];
            ldmx4(bhf, sb + SM_KHI + boff);
#pragma unroll
            for (int mt = 0; mt < 2; mt++)
#pragma unroll
                for (int hv = 0; hv < 2; hv++) {
                    int nt = ntp * 2 + hv;
                    mma16816h(C[mt][nt], ah[mt], bhf[hv], bhf[2 + hv]);   // qh*kh
                    mma16816h(C[mt][nt], al[mt], bhf[hv], bhf[2 + hv]);   // ql*kh
                }
        }
    }
    __syncthreads();   // tiles+As no longer needed; D_s may overwrite

    // ---- phase 4: C fragments -> D_s (slot-swizzled, conflict-free) ----
    {
        int lr = lane >> 2, lc2 = 2 * (lane & 3);
#pragma unroll
        for (int mt = 0; mt < 2; mt++)
#pragma unroll
            for (int nt = 0; nt < 8; nt++)
#pragma unroll
                for (int rh = 0; rh < 2; rh++) {
                    int row = warp_m * 32 + mt * 16 + rh * 8 + lr;
                    int cg = warp_n * 8 + nt;
                    int phys = (cg + row) & 15;
                    *(float2*)&D_s[row * 128 + phys * 8 + lc2] =
                        make_float2(C[mt][nt][rh * 2], C[mt][nt][rh * 2 + 1]);
                }
    }
    __syncthreads();

    // ---- phase 5: row-major epilogue with ids prefetch ----
    const int* idb = ids + ((size_t)b * LLEN + l0) * LLEN + m0;
    float* ob = out + ((size_t)bh * LLEN + l0) * LLEN + m0;
    int cg = lane >> 1, half4 = (lane & 1) * 4;
    const __nv_bfloat16* vt0 = vs_t + lane * 16;

    int4 idp = *(const int4*)(idb + (size_t)(warp * 16) * LLEN + lane * 4);
#pragma unroll
    for (int i = 0; i < 16; i++) {
        int row = warp * 16 + i;
        int4 idn = (i < 15)
            ? *(const int4*)(idb + (size_t)(row + 1) * LLEN + lane * 4) : idp;
        float4 base4 = *(const float4*)&D_s[row * 128 + ((cg + row) & 15) * 8 + half4];
        const __nv_bfloat16* urow = us_h + row * UVS;
        int idv[4] = {idp.x, idp.y, idp.z, idp.w};
        float basev[4] = {base4.x, base4.y, base4.z, base4.w};
        float res[4];
#pragma unroll
        for (int cc = 0; cc < 4; cc++) {
            int id = idv[cc];
            int rc = min(max(id, 0), RREL - 1);
            uint2 up = *(const uint2*)(urow + rc * 4);
            uint2 vp = *(const uint2*)(vt0 + rc * VST + cc * 4);
            __nv_bfloat162 u01 = *(__nv_bfloat162*)&up.x;
            __nv_bfloat162 u23 = *(__nv_bfloat162*)&up.y;
            __nv_bfloat162 v01 = *(__nv_bfloat162*)&vp.x;
            __nv_bfloat162 v23 = *(__nv_bfloat162*)&vp.y;
            __nv_bfloat162 prod = __hmul2(u01, v01);
            prod = __hfma2(u23, v23, prod);
            float low = __low2float(prod) + __high2float(prod);
            res[cc] = ((unsigned)id < RREL) ? (basev[cc] + low) : 0.f;
        }
        *(float4*)(ob + (size_t)row * LLEN + lane * 4) =
            make_float4(res[0], res[1], res[2], res[3]);
        idp = idn;
    }
}

extern "C" void kernel_launch(void* const* d_in, const int* in_sizes, int n_in,
                              void* d_out, int out_size) {
    const float* Q   = (const float*)d_in[0];
    const float* K   = (const float*)d_in[1];
    const int*   ids = (const int*)d_in[2];
    const float* A1  = (const float*)d_in[3];
    const float* A2  = (const float*)d_in[4];
    float* out = (float*)d_out;

    static int once = 0;
    if (!once) {
        cudaFuncSetAttribute(relmat_fused, cudaFuncAttributeMaxDynamicSharedMemorySize, DYN_SMEM);
        once = 1;
    }

    dim3 gmain(LLEN / 128, LLEN / 128, BB * HH);
    relmat_fused<<<gmain, 256, DYN_SMEM>>>(Q, K, ids, A1, A2, out);
}

// round 15
// speedup vs baseline: 1.2644x; 1.2644x over previous
#include <cuda_runtime.h>
#include <cuda_bf16.h>
#include <cuda_fp16.h>
#include <cstdint>

#define BB 2
#define HH 16
#define LLEN 1024
#define RREL 16

// precomputed low-rank projections, bf16, layout [bh][l][r*4+e]
__device__ __nv_bfloat16 g_u[(size_t)BB * HH * LLEN * 64];
__device__ __nv_bfloat16 g_v[(size_t)BB * HH * LLEN * 64];

// ---------------- helpers ----------------
__device__ __forceinline__ uint32_t smem_u32(const void* p) {
    uint32_t a;
    asm("{ .reg .u64 t; cvta.to.shared.u64 t, %1; cvt.u32.u64 %0, t; }" : "=r"(a) : "l"(p));
    return a;
}
#define SWZ(off) ((off) ^ (((off) >> 3) & 0x70))

__device__ __forceinline__ void ldmx4(uint32_t* r, uint32_t addr) {
    asm volatile("ldmatrix.sync.aligned.m8n8.x4.shared.b16 {%0,%1,%2,%3}, [%4];"
                 : "=r"(r[0]), "=r"(r[1]), "=r"(r[2]), "=r"(r[3]) : "r"(addr));
}
__device__ __forceinline__ void mma16816bf(float* c, const uint32_t* a,
                                           uint32_t b0, uint32_t b1) {
    asm volatile(
        "mma.sync.aligned.m16n8k16.row.col.f32.bf16.bf16.f32 "
        "{%0,%1,%2,%3}, {%4,%5,%6,%7}, {%8,%9}, {%0,%1,%2,%3};"
        : "+f"(c[0]), "+f"(c[1]), "+f"(c[2]), "+f"(c[3])
        : "r"(a[0]), "r"(a[1]), "r"(a[2]), "r"(a[3]), "r"(b0), "r"(b1));
}
__device__ __forceinline__ void mma16816h(float* c, const uint32_t* a,
                                          uint32_t b0, uint32_t b1) {
    asm volatile(
        "mma.sync.aligned.m16n8k16.row.col.f32.f16.f16.f32 "
        "{%0,%1,%2,%3}, {%4,%5,%6,%7}, {%8,%9}, {%0,%1,%2,%3};"
        : "+f"(c[0]), "+f"(c[1]), "+f"(c[2]), "+f"(c[3])
        : "r"(a[0]), "r"(a[1]), "r"(a[2]), "r"(a[3]), "r"(b0), "r"(b1));
}
__device__ __forceinline__ unsigned bf2pack(float x, float y) {
    __nv_bfloat162 h = __float22bfloat162_rn(make_float2(x, y));
    return *(unsigned*)&h;
}
__device__ __forceinline__ unsigned h2pack(float x, float y) {
    __half2 h = __floats2half2_rn(x, y);
    return *(unsigned*)&h;
}

// ---------------- precompute via mma: u = Q@A1, v = K@A2 (bf16) ----------------
// grid (2,16,32): x=uv, y=lblk(64 rows), z=bh. 128 threads = 4 warps, 16 rows each.
__global__ __launch_bounds__(128) void precompute_uv_mma(
    const float* __restrict__ Q, const float* __restrict__ K,
    const float* __restrict__ A1, const float* __restrict__ A2)
{
    __shared__ char psm[8192 + 8192];   // rows[64][64]bf16 @0, As[64][64]bf16 @8192
    uint32_t sb = smem_u32(psm);

    int uv = blockIdx.x, lblk = blockIdx.y, bh = blockIdx.z, h = bh & 15;
    int tid = threadIdx.x, lane = tid & 31, w = tid >> 5;

    // stage A slice -> As[oc][d], bf16, swizzled
    for (int t = tid; t < 4096; t += 128) {
        int r = t >> 8, rem = t & 255;
        int oc, d;
        float a;
        if (uv == 0) { d = rem >> 2; oc = r * 4 + (rem & 3);
                       a = A1[(size_t)(r * HH + h) * 256 + rem]; }
        else         { oc = r * 4 + (rem >> 6); d = rem & 63;
                       a = A2[(size_t)(r * HH + h) * 256 + rem]; }
        *(__nv_bfloat16*)(psm + 8192 + SWZ((uint32_t)(oc * 128 + d * 2))) =
            __float2bfloat16(a);
    }
    // stage 64-row tile (fp32 -> bf16), swizzled
    const float* src = (uv == 0 ? Q : K) + ((size_t)bh * LLEN + lblk * 64) * 64;
#pragma unroll
    for (int it = 0; it < 8; it++) {
        int idx = tid + 128 * it;          // [0,1024): 64 rows x 16 col-quads
        int row = idx >> 4, c4 = idx & 15;
        float4 v = *(const float4*)(src + (size_t)row * 64 + c4 * 4);
        *(uint2*)(psm + SWZ((uint32_t)(row * 128 + c4 * 8))) =
            make_uint2(bf2pack(v.x, v.y), bf2pack(v.z, v.w));
    }
    __syncthreads();

    float C[8][4];
#pragma unroll
    for (int nt = 0; nt < 8; nt++)
#pragma unroll
        for (int q = 0; q < 4; q++) C[nt][q] = 0.f;

    int lrowA = w * 16 + (lane & 15);
    int lrowB = (lane & 15);
    int kb = lane >> 4;

#pragma unroll
    for (int ks = 0; ks < 4; ks++) {
        uint32_t kcol = (uint32_t)((ks * 2 + kb) * 16);
        uint32_t af[4];
        ldmx4(af, sb + SWZ((uint32_t)(lrowA * 128) + kcol));
#pragma unroll
        for (int ntp = 0; ntp < 4; ntp++) {
            uint32_t bf[4];
            ldmx4(bf, sb + 8192 + SWZ((uint32_t)((lrowB + ntp * 16) * 128) + kcol));
#pragma unroll
            for (int hv = 0; hv < 2; hv++)
                mma16816bf(C[ntp * 2 + hv], af, bf[hv], bf[2 + hv]);
        }
    }

    __nv_bfloat16* dst = (uv == 0 ? g_u : g_v) + ((size_t)bh * LLEN + lblk * 64) * 64;
    int r0 = w * 16 + (lane >> 2), c0 = 2 * (lane & 3);
#pragma unroll
    for (int nt = 0; nt < 8; nt++) {
        *(unsigned*)&dst[(size_t)r0 * 64 + nt * 8 + c0] = bf2pack(C[nt][0], C[nt][1]);
        *(unsigned*)&dst[(size_t)(r0 + 8) * 64 + nt * 8 + c0] = bf2pack(C[nt][2], C[nt][3]);
    }
}

// ---------------- main kernel (R10 structure) ----------------
// smem (104448 B dynamic):
//   us  bf16[128][UVS=72] @ 0        (18432)
//   v_t bf16[16][VST=516] @ 18432    (16512)
//   tiles @ 38912: QHI(16K) QLO(16K) KHI(16K)  [fp16, GEMM phase]
//   D_s fp32[128][128] slot-swizzled @ 38912   [epilogue, aliases tiles]
#define UVS 72
#define VST 516
#define SM_VT 18432
#define SM_TB 38912
#define SM_QHI (SM_TB + 0)
#define SM_QLO (SM_TB + 16384)
#define SM_KHI (SM_TB + 32768)
#define DYN_SMEM (SM_TB + 65536)

__global__ __launch_bounds__(256, 2) void relmat_main(
    const float* __restrict__ Q, const float* __restrict__ K,
    const int* __restrict__ ids, float* __restrict__ out)
{
    extern __shared__ char sm8[];
    uint32_t sb = smem_u32(sm8);
    __nv_bfloat16* us_h = (__nv_bfloat16*)(sm8);
    __nv_bfloat16* vs_t = (__nv_bfloat16*)(sm8 + SM_VT);
    float* D_s = (float*)(sm8 + SM_TB);

    int bh = blockIdx.z, b = bh >> 4;
    int l0 = blockIdx.y * 128, m0 = blockIdx.x * 128;
    int tid = threadIdx.x, lane = tid & 31, warp = tid >> 5;
    int warp_m = warp & 3, warp_n = warp >> 2;   // 4x2 warp grid, warp tile 32x64

    // ---- phase 1: stage u/v; load Q (fp16 hi+lo) and K (fp16 hi) swizzled ----
    {
        const uint4* ub = (const uint4*)(g_u + ((size_t)bh * LLEN + l0) * 64);
        const uint4* vb = (const uint4*)(g_v + ((size_t)bh * LLEN + m0) * 64);
#pragma unroll
        for (int it = 0; it < 8; it++) {
            int idx = tid + 256 * it;
            int mat = idx >> 10, rr = (idx >> 3) & 127, cc = idx & 7;
            uint4 val = (mat ? vb : ub)[rr * 8 + cc];
            if (mat) {
                *(uint2*)&vs_t[(2 * cc) * VST + rr * 4]     = make_uint2(val.x, val.y);
                *(uint2*)&vs_t[(2 * cc + 1) * VST + rr * 4] = make_uint2(val.z, val.w);
            } else {
                *(uint4*)(us_h + rr * UVS + cc * 8) = val;
            }
        }
    }
    const float* Qb = Q + ((size_t)bh * LLEN + l0) * 64;
    const float* Kb = K + ((size_t)bh * LLEN + m0) * 64;
#pragma unroll
    for (int it = 0; it < 8; it++) {
        int idx = tid + 256 * it;
        int row = idx >> 4, c4 = idx & 15;
        uint32_t off = SWZ((uint32_t)(row * 128 + c4 * 8));
        {
            float4 v = *(const float4*)(Qb + (size_t)row * 64 + c4 * 4);
            __half2 h0 = __floats2half2_rn(v.x, v.y);
            __half2 h1 = __floats2half2_rn(v.z, v.w);
            float2 r0 = make_float2(v.x - __half2float(__low2half(h0)),
                                    v.y - __half2float(__high2half(h0)));
            float2 r1 = make_float2(v.z - __half2float(__low2half(h1)),
                                    v.w - __half2float(__high2half(h1)));
            *(uint2*)(sm8 + SM_QHI + off) = make_uint2(*(unsigned*)&h0, *(unsigned*)&h1);
            *(uint2*)(sm8 + SM_QLO + off) = make_uint2(h2pack(r0.x, r0.y), h2pack(r1.x, r1.y));
        }
        {
            float4 v = *(const float4*)(Kb + (size_t)row * 64 + c4 * 4);
            *(uint2*)(sm8 + SM_KHI + off) = make_uint2(h2pack(v.x, v.y), h2pack(v.z, v.w));
        }
    }
    __syncthreads();

    // ---- phase 2: GEMM, 2 fp16 passes fused per k-step ----
    float C[2][8][4];
#pragma unroll
    for (int mt = 0; mt < 2; mt++)
#pragma unroll
        for (int nt = 0; nt < 8; nt++)
#pragma unroll
            for (int q = 0; q < 4; q++) C[mt][nt][q] = 0.f;

    int lrowA = warp_m * 32 + (lane & 15);
    int lrowB = warp_n * 64 + (lane & 15);
    int kb = (lane >> 4);

#pragma unroll
    for (int ks = 0; ks < 4; ks++) {
        uint32_t kcol = (uint32_t)((ks * 2 + kb) * 16);
        uint32_t ah[2][4], al[2][4];
#pragma unroll
        for (int mt = 0; mt < 2; mt++) {
            uint32_t aoff = SWZ((uint32_t)((lrowA + mt * 16) * 128) + kcol);
            ldmx4(ah[mt], sb + SM_QHI + aoff);
            ldmx4(al[mt], sb + SM_QLO + aoff);
        }
#pragma unroll
        for (int ntp = 0; ntp < 4; ntp++) {
            uint32_t boff = SWZ((uint32_t)((lrowB + ntp * 16) * 128) + kcol);
            uint32_t bhf[4];
            ldmx4(bhf, sb + SM_KHI + boff);
#pragma unroll
            for (int mt = 0; mt < 2; mt++)
#pragma unroll
                for (int hv = 0; hv < 2; hv++) {
                    int nt = ntp * 2 + hv;
                    mma16816h(C[mt][nt], ah[mt], bhf[hv], bhf[2 + hv]);   // qh*kh
                    mma16816h(C[mt][nt], al[mt], bhf[hv], bhf[2 + hv]);   // ql*kh
                }
        }
    }
    __syncthreads();

    // ---- phase 3: C fragments -> D_s (slot-swizzled, conflict-free) ----
    {
        int lr = lane >> 2, lc2 = 2 * (lane & 3);
#pragma unroll
        for (int mt = 0; mt < 2; mt++)
#pragma unroll
            for (int nt = 0; nt < 8; nt++)
#pragma unroll
                for (int rh = 0; rh < 2; rh++) {
                    int row = warp_m * 32 + mt * 16 + rh * 8 + lr;
                    int cg = warp_n * 8 + nt;
                    int phys = (cg + row) & 15;
                    *(float2*)&D_s[row * 128 + phys * 8 + lc2] =
                        make_float2(C[mt][nt][rh * 2], C[mt][nt][rh * 2 + 1]);
                }
    }
    __syncthreads();

    // ---- phase 4: row-major epilogue, ids prefetch distance 2 ----
    const int* idb = ids + ((size_t)b * LLEN + l0) * LLEN + m0;
    float* ob = out + ((size_t)bh * LLEN + l0) * LLEN + m0;
    int cg = lane >> 1, half4 = (lane & 1) * 4;
    const __nv_bfloat16* vt0 = vs_t + lane * 16;

    int4 idbuf[2];
    idbuf[0] = *(const int4*)(idb + (size_t)(warp * 16) * LLEN + lane * 4);
    idbuf[1] = *(const int4*)(idb + (size_t)(warp * 16 + 1) * LLEN + lane * 4);
#pragma unroll
    for (int i = 0; i < 16; i++) {
        int row = warp * 16 + i;
        int4 idp = idbuf[i & 1];
        if (i < 14)
            idbuf[i & 1] = *(const int4*)(idb + (size_t)(row + 2) * LLEN + lane * 4);
        float4 base4 = *(const float4*)&D_s[row * 128 + ((cg + row) & 15) * 8 + half4];
        const __nv_bfloat16* urow = us_h + row * UVS;
        int idv[4] = {idp.x, idp.y, idp.z, idp.w};
        float basev[4] = {base4.x, base4.y, base4.z, base4.w};
        float res[4];
#pragma unroll
        for (int cc = 0; cc < 4; cc++) {
            int id = idv[cc];
            int rc = min(max(id, 0), RREL - 1);
            uint2 up = *(const uint2*)(urow + rc * 4);
            uint2 vp = *(const uint2*)(vt0 + rc * VST + cc * 4);
            __nv_bfloat162 u01 = *(__nv_bfloat162*)&up.x;
            __nv_bfloat162 u23 = *(__nv_bfloat162*)&up.y;
            __nv_bfloat162 v01 = *(__nv_bfloat162*)&vp.x;
            __nv_bfloat162 v23 = *(__nv_bfloat162*)&vp.y;
            __nv_bfloat162 prod = __hmul2(u01, v01);
            prod = __hfma2(u23, v23, prod);
            float low = __low2float(prod) + __high2float(prod);
            res[cc] = ((unsigned)id < RREL) ? (basev[cc] + low) : 0.f;
        }
        *(float4*)(ob + (size_t)row * LLEN + lane * 4) =
            make_float4(res[0], res[1], res[2], res[3]);
    }
}

extern "C" void kernel_launch(void* const* d_in, const int* in_sizes, int n_in,
                              void* d_out, int out_size) {
    const float* Q   = (const float*)d_in[0];
    const float* K   = (const float*)d_in[1];
    const int*   ids = (const int*)d_in[2];
    const float* A1  = (const float*)d_in[3];
    const float* A2  = (const float*)d_in[4];
    float* out = (float*)d_out;

    static int once = 0;
    if (!once) {
        cudaFuncSetAttribute(relmat_main, cudaFuncAttributeMaxDynamicSharedMemorySize, DYN_SMEM);
        once = 1;
    }

    dim3 gpre(2, 16, BB * HH);
    precompute_uv_mma<<<gpre, 128>>>(Q, K, A1, A2);

    dim3 gmain(LLEN / 128, LLEN / 128, BB * HH);
    relmat_main<<<gmain, 256, DYN_SMEM>>>(Q, K, ids, out);
}

// round 16
// speedup vs baseline: 1.2902x; 1.0204x over previous
#include <cuda_runtime.h>
#include <cuda_bf16.h>
#include <cuda_fp16.h>
#include <cstdint>

#define BB 2
#define HH 16
#define LLEN 1024
#define RREL 16

// precomputed low-rank projections, bf16, layout [bh][l][r*4+e]
__device__ __nv_bfloat16 g_u[(size_t)BB * HH * LLEN * 64];
__device__ __nv_bfloat16 g_v[(size_t)BB * HH * LLEN * 64];

// ---------------- helpers ----------------
__device__ __forceinline__ uint32_t smem_u32(const void* p) {
    uint32_t a;
    asm("{ .reg .u64 t; cvta.to.shared.u64 t, %1; cvt.u32.u64 %0, t; }" : "=r"(a) : "l"(p));
    return a;
}
#define SWZ(off) ((off) ^ (((off) >> 3) & 0x70))

__device__ __forceinline__ void ldmx4(uint32_t* r, uint32_t addr) {
    asm volatile("ldmatrix.sync.aligned.m8n8.x4.shared.b16 {%0,%1,%2,%3}, [%4];"
                 : "=r"(r[0]), "=r"(r[1]), "=r"(r[2]), "=r"(r[3]) : "r"(addr));
}
__device__ __forceinline__ void mma16816bf(float* c, const uint32_t* a,
                                           uint32_t b0, uint32_t b1) {
    asm volatile(
        "mma.sync.aligned.m16n8k16.row.col.f32.bf16.bf16.f32 "
        "{%0,%1,%2,%3}, {%4,%5,%6,%7}, {%8,%9}, {%0,%1,%2,%3};"
        : "+f"(c[0]), "+f"(c[1]), "+f"(c[2]), "+f"(c[3])
        : "r"(a[0]), "r"(a[1]), "r"(a[2]), "r"(a[3]), "r"(b0), "r"(b1));
}
__device__ __forceinline__ void mma16816h(float* c, const uint32_t* a,
                                          uint32_t b0, uint32_t b1) {
    asm volatile(
        "mma.sync.aligned.m16n8k16.row.col.f32.f16.f16.f32 "
        "{%0,%1,%2,%3}, {%4,%5,%6,%7}, {%8,%9}, {%0,%1,%2,%3};"
        : "+f"(c[0]), "+f"(c[1]), "+f"(c[2]), "+f"(c[3])
        : "r"(a[0]), "r"(a[1]), "r"(a[2]), "r"(a[3]), "r"(b0), "r"(b1));
}
__device__ __forceinline__ unsigned bf2pack(float x, float y) {
    __nv_bfloat162 h = __float22bfloat162_rn(make_float2(x, y));
    return *(unsigned*)&h;
}
__device__ __forceinline__ unsigned h2pack(float x, float y) {
    __half2 h = __floats2half2_rn(x, y);
    return *(unsigned*)&h;
}

// ---------------- precompute via mma: u = Q@A1, v = K@A2 (bf16) ----------------
// grid (2,16,32): x=uv, y=lblk(64 rows), z=bh. 128 threads = 4 warps.
__global__ __launch_bounds__(128) void precompute_uv_mma(
    const float* __restrict__ Q, const float* __restrict__ K,
    const float* __restrict__ A1, const float* __restrict__ A2)
{
    __shared__ char psm[8192 + 8192];   // rows[64][64]bf16 @0, As[64][64]bf16 @8192
    uint32_t sb = smem_u32(psm);

    int uv = blockIdx.x, lblk = blockIdx.y, bh = blockIdx.z, h = bh & 15;
    int tid = threadIdx.x, lane = tid & 31, w = tid >> 5;

    for (int t = tid; t < 4096; t += 128) {
        int r = t >> 8, rem = t & 255;
        int oc, d;
        float a;
        if (uv == 0) { d = rem >> 2; oc = r * 4 + (rem & 3);
                       a = A1[(size_t)(r * HH + h) * 256 + rem]; }
        else         { oc = r * 4 + (rem >> 6); d = rem & 63;
                       a = A2[(size_t)(r * HH + h) * 256 + rem]; }
        *(__nv_bfloat16*)(psm + 8192 + SWZ((uint32_t)(oc * 128 + d * 2))) =
            __float2bfloat16(a);
    }
    const float* src = (uv == 0 ? Q : K) + ((size_t)bh * LLEN + lblk * 64) * 64;
#pragma unroll
    for (int it = 0; it < 8; it++) {
        int idx = tid + 128 * it;
        int row = idx >> 4, c4 = idx & 15;
        float4 v = *(const float4*)(src + (size_t)row * 64 + c4 * 4);
        *(uint2*)(psm + SWZ((uint32_t)(row * 128 + c4 * 8))) =
            make_uint2(bf2pack(v.x, v.y), bf2pack(v.z, v.w));
    }
    __syncthreads();

    float C[8][4];
#pragma unroll
    for (int nt = 0; nt < 8; nt++)
#pragma unroll
        for (int q = 0; q < 4; q++) C[nt][q] = 0.f;

    int lrowA = w * 16 + (lane & 15);
    int lrowB = (lane & 15);
    int kb = lane >> 4;

#pragma unroll
    for (int ks = 0; ks < 4; ks++) {
        uint32_t kcol = (uint32_t)((ks * 2 + kb) * 16);
        uint32_t af[4];
        ldmx4(af, sb + SWZ((uint32_t)(lrowA * 128) + kcol));
#pragma unroll
        for (int ntp = 0; ntp < 4; ntp++) {
            uint32_t bf[4];
            ldmx4(bf, sb + 8192 + SWZ((uint32_t)((lrowB + ntp * 16) * 128) + kcol));
#pragma unroll
            for (int hv = 0; hv < 2; hv++)
                mma16816bf(C[ntp * 2 + hv], af, bf[hv], bf[2 + hv]);
        }
    }

    __nv_bfloat16* dst = (uv == 0 ? g_u : g_v) + ((size_t)bh * LLEN + lblk * 64) * 64;
    int r0 = w * 16 + (lane >> 2), c0 = 2 * (lane & 3);
#pragma unroll
    for (int nt = 0; nt < 8; nt++) {
        *(unsigned*)&dst[(size_t)r0 * 64 + nt * 8 + c0] = bf2pack(C[nt][0], C[nt][1]);
        *(unsigned*)&dst[(size_t)(r0 + 8) * 64 + nt * 8 + c0] = bf2pack(C[nt][2], C[nt][3]);
    }
}

// ---------------- main kernel: 64(l) x 128(m) tile, 3 CTAs/SM ----------------
// smem (58496 B dynamic):
//   us  bf16[64][UVS=72] @ 0        (9216)
//   v_t bf16[16][VST=516] @ 9216    (16512)
//   tiles @ 25728 (SM_TB): QHI(8K) QLO(8K) KHI(16K)   [GEMM phase]
//   D_s fp32[64][128] slot-swizzled @ SM_TB (32K)      [epilogue, aliases tiles]
#define UVS 72
#define VST 516
#define SM_VT 9216
#define SM_TB 25728
#define SM_QHI (SM_TB + 0)
#define SM_QLO (SM_TB + 8192)
#define SM_KHI (SM_TB + 16384)
#define DYN_SMEM (SM_TB + 32768)

__global__ __launch_bounds__(256, 3) void relmat_main(
    const float* __restrict__ Q, const float* __restrict__ K,
    const int* __restrict__ ids, float* __restrict__ out)
{
    extern __shared__ char sm8[];
    uint32_t sb = smem_u32(sm8);
    __nv_bfloat16* us_h = (__nv_bfloat16*)(sm8);
    __nv_bfloat16* vs_t = (__nv_bfloat16*)(sm8 + SM_VT);
    float* D_s = (float*)(sm8 + SM_TB);

    int bh = blockIdx.z, b = bh >> 4;
    int l0 = blockIdx.y * 64, m0 = blockIdx.x * 128;
    int tid = threadIdx.x, lane = tid & 31, warp = tid >> 5;
    int warp_m = warp & 1, warp_n = warp >> 1;   // 2x4 warp grid, warp tile 32x32

    // ---- phase 1: stage u (64 rows) / v (128 rows); Q hi+lo (64), K hi (128) ----
    {
        const uint4* ub = (const uint4*)(g_u + ((size_t)bh * LLEN + l0) * 64);
        const uint4* vb = (const uint4*)(g_v + ((size_t)bh * LLEN + m0) * 64);
#pragma unroll
        for (int it = 0; it < 6; it++) {
            int idx = tid + 256 * it;          // [0,1536): 512 u + 1024 v
            if (idx < 512) {
                int rr = idx >> 3, cc = idx & 7;
                *(uint4*)(us_h + rr * UVS + cc * 8) = ub[idx];
            } else {
                int j = idx - 512;
                int rr = j >> 3, cc = j & 7;
                uint4 val = vb[j];
                *(uint2*)&vs_t[(2 * cc) * VST + rr * 4]     = make_uint2(val.x, val.y);
                *(uint2*)&vs_t[(2 * cc + 1) * VST + rr * 4] = make_uint2(val.z, val.w);
            }
        }
    }
    const float* Qb = Q + ((size_t)bh * LLEN + l0) * 64;
    const float* Kb = K + ((size_t)bh * LLEN + m0) * 64;
    // Q: 64 rows, hi + residual
#pragma unroll
    for (int it = 0; it < 4; it++) {
        int idx = tid + 256 * it;              // [0,1024)
        int row = idx >> 4, c4 = idx & 15;
        uint32_t off = SWZ((uint32_t)(row * 128 + c4 * 8));
        float4 v = *(const float4*)(Qb + (size_t)row * 64 + c4 * 4);
        __half2 h0 = __floats2half2_rn(v.x, v.y);
        __half2 h1 = __floats2half2_rn(v.z, v.w);
        float2 r0 = make_float2(v.x - __half2float(__low2half(h0)),
                                v.y - __half2float(__high2half(h0)));
        float2 r1 = make_float2(v.z - __half2float(__low2half(h1)),
                                v.w - __half2float(__high2half(h1)));
        *(uint2*)(sm8 + SM_QHI + off) = make_uint2(*(unsigned*)&h0, *(unsigned*)&h1);
        *(uint2*)(sm8 + SM_QLO + off) = make_uint2(h2pack(r0.x, r0.y), h2pack(r1.x, r1.y));
    }
    // K: 128 rows, hi only
#pragma unroll
    for (int it = 0; it < 8; it++) {
        int idx = tid + 256 * it;              // [0,2048)
        int row = idx >> 4, c4 = idx & 15;
        uint32_t off = SWZ((uint32_t)(row * 128 + c4 * 8));
        float4 v = *(const float4*)(Kb + (size_t)row * 64 + c4 * 4);
        *(uint2*)(sm8 + SM_KHI + off) = make_uint2(h2pack(v.x, v.y), h2pack(v.z, v.w));
    }
    __syncthreads();

    // ---- phase 2: GEMM, 2 fp16 passes fused per k-step ----
    float C[2][4][4];
#pragma unroll
    for (int mt = 0; mt < 2; mt++)
#pragma unroll
        for (int nt = 0; nt < 4; nt++)
#pragma unroll
            for (int q = 0; q < 4; q++) C[mt][nt][q] = 0.f;

    int lrowA = warp_m * 32 + (lane & 15);
    int lrowB = warp_n * 32 + (lane & 15);
    int kb = (lane >> 4);

#pragma unroll
    for (int ks = 0; ks < 4; ks++) {
        uint32_t kcol = (uint32_t)((ks * 2 + kb) * 16);
        uint32_t ah[2][4], al[2][4];
#pragma unroll
        for (int mt = 0; mt < 2; mt++) {
            uint32_t aoff = SWZ((uint32_t)((lrowA + mt * 16) * 128) + kcol);
            ldmx4(ah[mt], sb + SM_QHI + aoff);
            ldmx4(al[mt], sb + SM_QLO + aoff);
        }
#pragma unroll
        for (int ntp = 0; ntp < 2; ntp++) {
            uint32_t boff = SWZ((uint32_t)((lrowB + ntp * 16) * 128) + kcol);
            uint32_t bhf[4];
            ldmx4(bhf, sb + SM_KHI + boff);
#pragma unroll
            for (int mt = 0; mt < 2; mt++)
#pragma unroll
                for (int hv = 0; hv < 2; hv++) {
                    int nt = ntp * 2 + hv;
                    mma16816h(C[mt][nt], ah[mt], bhf[hv], bhf[2 + hv]);   // qh*kh
                    mma16816h(C[mt][nt], al[mt], bhf[hv], bhf[2 + hv]);   // ql*kh
                }
        }
    }
    __syncthreads();   // tiles no longer needed; D_s may overwrite

    // ---- phase 3: C fragments -> D_s (slot-swizzled) ----
    {
        int lr = lane >> 2, lc2 = 2 * (lane & 3);
#pragma unroll
        for (int mt = 0; mt < 2; mt++)
#pragma unroll
            for (int nt = 0; nt < 4; nt++)
#pragma unroll
                for (int rh = 0; rh < 2; rh++) {
                    int row = warp_m * 32 + mt * 16 + rh * 8 + lr;
                    int cg = warp_n * 4 + nt;
                    int phys = (cg + row) & 15;
                    *(float2*)&D_s[row * 128 + phys * 8 + lc2] =
                        make_float2(C[mt][nt][rh * 2], C[mt][nt][rh * 2 + 1]);
                }
    }
    __syncthreads();

    // ---- phase 4: row-major epilogue, 8 rows/warp, ids prefetch ----
    const int* idb = ids + ((size_t)b * LLEN + l0) * LLEN + m0;
    float* ob = out + ((size_t)bh * LLEN + l0) * LLEN + m0;
    int cg = lane >> 1, half4 = (lane & 1) * 4;
    const __nv_bfloat16* vt0 = vs_t + lane * 16;

    int4 idbuf[2];
    idbuf[0] = *(const int4*)(idb + (size_t)(warp * 8) * LLEN + lane * 4);
    idbuf[1] = *(const int4*)(idb + (size_t)(warp * 8 + 1) * LLEN + lane * 4);
#pragma unroll
    for (int i = 0; i < 8; i++) {
        int row = warp * 8 + i;
        int4 idp = idbuf[i & 1];
        if (i < 6)
            idbuf[i & 1] = *(const int4*)(idb + (size_t)(row + 2) * LLEN + lane * 4);
        float4 base4 = *(const float4*)&D_s[row * 128 + ((cg + row) & 15) * 8 + half4];
        const __nv_bfloat16* urow = us_h + row * UVS;
        int idv[4] = {idp.x, idp.y, idp.z, idp.w};
        float basev[4] = {base4.x, base4.y, base4.z, base4.w};
        float res[4];
#pragma unroll
        for (int cc = 0; cc < 4; cc++) {
            int id = idv[cc];
            int rc = min(max(id, 0), RREL - 1);
            uint2 up = *(const uint2*)(urow + rc * 4);
            uint2 vp = *(const uint2*)(vt0 + rc * VST + cc * 4);
            __nv_bfloat162 u01 = *(__nv_bfloat162*)&up.x;
            __nv_bfloat162 u23 = *(__nv_bfloat162*)&up.y;
            __nv_bfloat162 v01 = *(__nv_bfloat162*)&vp.x;
            __nv_bfloat162 v23 = *(__nv_bfloat162*)&vp.y;
            __nv_bfloat162 prod = __hmul2(u01, v01);
            prod = __hfma2(u23, v23, prod);
            float low = __low2float(prod) + __high2float(prod);
            res[cc] = ((unsigned)id < RREL) ? (basev[cc] + low) : 0.f;
        }
        *(float4*)(ob + (size_t)row * LLEN + lane * 4) =
            make_float4(res[0], res[1], res[2], res[3]);
    }
}

extern "C" void kernel_launch(void* const* d_in, const int* in_sizes, int n_in,
                              void* d_out, int out_size) {
    const float* Q   = (const float*)d_in[0];
    const float* K   = (const float*)d_in[1];
    const int*   ids = (const int*)d_in[2];
    const float* A1  = (const float*)d_in[3];
    const float* A2  = (const float*)d_in[4];
    float* out = (float*)d_out;

    static int once = 0;
    if (!once) {
        cudaFuncSetAttribute(relmat_main, cudaFuncAttributeMaxDynamicSharedMemorySize, DYN_SMEM);
        once = 1;
    }

    dim3 gpre(2, 16, BB * HH);
    precompute_uv_mma<<<gpre, 128>>>(Q, K, A1, A2);

    dim3 gmain(LLEN / 128, LLEN / 64, BB * HH);
    relmat_main<<<gmain, 256, DYN_SMEM>>>(Q, K, ids, out);
}

// round 17
// speedup vs baseline: 1.3818x; 1.0710x over previous
#include <cuda_runtime.h>
#include <cuda_bf16.h>
#include <cuda_fp16.h>
#include <cstdint>

#define BB 2
#define HH 16
#define LLEN 1024
#define RREL 16

// precomputed low-rank projections, bf16, layout [bh][l][r*4+e]
__device__ __nv_bfloat16 g_u[(size_t)BB * HH * LLEN * 64];
__device__ __nv_bfloat16 g_v[(size_t)BB * HH * LLEN * 64];
// precomputed fp16 planes of Q (hi+residual) and K (hi), layout [bh][l][64]
__device__ __half g_qh[(size_t)BB * HH * LLEN * 64];
__device__ __half g_ql[(size_t)BB * HH * LLEN * 64];
__device__ __half g_kh[(size_t)BB * HH * LLEN * 64];

// ---------------- helpers ----------------
__device__ __forceinline__ uint32_t smem_u32(const void* p) {
    uint32_t a;
    asm("{ .reg .u64 t; cvta.to.shared.u64 t, %1; cvt.u32.u64 %0, t; }" : "=r"(a) : "l"(p));
    return a;
}
#define SWZ(off) ((off) ^ (((off) >> 3) & 0x70))

__device__ __forceinline__ void cp16(uint32_t d, const void* s) {
    asm volatile("cp.async.cg.shared.global [%0], [%1], 16;" :: "r"(d), "l"(s));
}
__device__ __forceinline__ void cp8(uint32_t d, const void* s) {
    asm volatile("cp.async.ca.shared.global [%0], [%1], 8;" :: "r"(d), "l"(s));
}
__device__ __forceinline__ void cp_wait_all() {
    asm volatile("cp.async.commit_group;");
    asm volatile("cp.async.wait_group 0;" ::: "memory");
}

__device__ __forceinline__ void ldmx4(uint32_t* r, uint32_t addr) {
    asm volatile("ldmatrix.sync.aligned.m8n8.x4.shared.b16 {%0,%1,%2,%3}, [%4];"
                 : "=r"(r[0]), "=r"(r[1]), "=r"(r[2]), "=r"(r[3]) : "r"(addr));
}
__device__ __forceinline__ void mma16816bf(float* c, const uint32_t* a,
                                           uint32_t b0, uint32_t b1) {
    asm volatile(
        "mma.sync.aligned.m16n8k16.row.col.f32.bf16.bf16.f32 "
        "{%0,%1,%2,%3}, {%4,%5,%6,%7}, {%8,%9}, {%0,%1,%2,%3};"
        : "+f"(c[0]), "+f"(c[1]), "+f"(c[2]), "+f"(c[3])
        : "r"(a[0]), "r"(a[1]), "r"(a[2]), "r"(a[3]), "r"(b0), "r"(b1));
}
__device__ __forceinline__ void mma16816h(float* c, const uint32_t* a,
                                          uint32_t b0, uint32_t b1) {
    asm volatile(
        "mma.sync.aligned.m16n8k16.row.col.f32.f16.f16.f32 "
        "{%0,%1,%2,%3}, {%4,%5,%6,%7}, {%8,%9}, {%0,%1,%2,%3};"
        : "+f"(c[0]), "+f"(c[1]), "+f"(c[2]), "+f"(c[3])
        : "r"(a[0]), "r"(a[1]), "r"(a[2]), "r"(a[3]), "r"(b0), "r"(b1));
}
__device__ __forceinline__ unsigned bf2pack(float x, float y) {
    __nv_bfloat162 h = __float22bfloat162_rn(make_float2(x, y));
    return *(unsigned*)&h;
}

// ---------------- precompute: u/v (bf16, via mma) + fp16 planes of Q/K ----------------
// grid (2,16,32): x=uv, y=lblk(64 rows), z=bh. 128 threads = 4 warps.
__global__ __launch_bounds__(128) void precompute_uv_mma(
    const float* __restrict__ Q, const float* __restrict__ K,
    const float* __restrict__ A1, const float* __restrict__ A2)
{
    __shared__ char psm[8192 + 8192];   // rows[64][64]bf16 @0, As[64][64]bf16 @8192
    uint32_t sb = smem_u32(psm);

    int uv = blockIdx.x, lblk = blockIdx.y, bh = blockIdx.z, h = bh & 15;
    int tid = threadIdx.x, lane = tid & 31, w = tid >> 5;

    for (int t = tid; t < 4096; t += 128) {
        int r = t >> 8, rem = t & 255;
        int oc, d;
        float a;
        if (uv == 0) { d = rem >> 2; oc = r * 4 + (rem & 3);
                       a = A1[(size_t)(r * HH + h) * 256 + rem]; }
        else         { oc = r * 4 + (rem >> 6); d = rem & 63;
                       a = A2[(size_t)(r * HH + h) * 256 + rem]; }
        *(__nv_bfloat16*)(psm + 8192 + SWZ((uint32_t)(oc * 128 + d * 2))) =
            __float2bfloat16(a);
    }
    size_t rowbase = (size_t)bh * LLEN + lblk * 64;
    const float* src = (uv == 0 ? Q : K) + rowbase * 64;
#pragma unroll
    for (int it = 0; it < 8; it++) {
        int idx = tid + 128 * it;              // [0,1024): 64 rows x 16 col-quads
        int row = idx >> 4, c4 = idx & 15;
        float4 v = *(const float4*)(src + (size_t)row * 64 + c4 * 4);
        // bf16 copy for the uv-mma below
        *(uint2*)(psm + SWZ((uint32_t)(row * 128 + c4 * 8))) =
            make_uint2(bf2pack(v.x, v.y), bf2pack(v.z, v.w));
        // fp16 planes for the main kernel
        __half2 h0 = __floats2half2_rn(v.x, v.y);
        __half2 h1 = __floats2half2_rn(v.z, v.w);
        size_t gofs = (rowbase + row) * 64 + c4 * 4;
        if (uv == 0) {
            float2 r0 = make_float2(v.x - __half2float(__low2half(h0)),
                                    v.y - __half2float(__high2half(h0)));
            float2 r1 = make_float2(v.z - __half2float(__low2half(h1)),
                                    v.w - __half2float(__high2half(h1)));
            __half2 l0 = __floats2half2_rn(r0.x, r0.y);
            __half2 l1 = __floats2half2_rn(r1.x, r1.y);
            *(uint2*)(g_qh + gofs) = make_uint2(*(unsigned*)&h0, *(unsigned*)&h1);
            *(uint2*)(g_ql + gofs) = make_uint2(*(unsigned*)&l0, *(unsigned*)&l1);
        } else {
            *(uint2*)(g_kh + gofs) = make_uint2(*(unsigned*)&h0, *(unsigned*)&h1);
        }
    }
    __syncthreads();

    float C[8][4];
#pragma unroll
    for (int nt = 0; nt < 8; nt++)
#pragma unroll
        for (int q = 0; q < 4; q++) C[nt][q] = 0.f;

    int lrowA = w * 16 + (lane & 15);
    int lrowB = (lane & 15);
    int kb = lane >> 4;

#pragma unroll
    for (int ks = 0; ks < 4; ks++) {
        uint32_t kcol = (uint32_t)((ks * 2 + kb) * 16);
        uint32_t af[4];
        ldmx4(af, sb + SWZ((uint32_t)(lrowA * 128) + kcol));
#pragma unroll
        for (int ntp = 0; ntp < 4; ntp++) {
            uint32_t bf[4];
            ldmx4(bf, sb + 8192 + SWZ((uint32_t)((lrowB + ntp * 16) * 128) + kcol));
#pragma unroll
            for (int hv = 0; hv < 2; hv++)
                mma16816bf(C[ntp * 2 + hv], af, bf[hv], bf[2 + hv]);
        }
    }

    __nv_bfloat16* dst = (uv == 0 ? g_u : g_v) + rowbase * 64;
    int r0 = w * 16 + (lane >> 2), c0 = 2 * (lane & 3);
#pragma unroll
    for (int nt = 0; nt < 8; nt++) {
        *(unsigned*)&dst[(size_t)r0 * 64 + nt * 8 + c0] = bf2pack(C[nt][0], C[nt][1]);
        *(unsigned*)&dst[(size_t)(r0 + 8) * 64 + nt * 8 + c0] = bf2pack(C[nt][2], C[nt][3]);
    }
}

// ---------------- main kernel: 64(l) x 128(m) tile, 3 CTAs/SM, cp.async staging ----------------
// smem (58496 B dynamic):
//   us  bf16[64][UVS=72] @ 0        (9216)
//   v_t bf16[16][VST=516] @ 9216    (16512)
//   tiles @ 25728 (SM_TB): QHI(8K) QLO(8K) KHI(16K)   [GEMM phase]
//   D_s fp32[64][128] slot-swizzled @ SM_TB (32K)      [epilogue, aliases tiles]
#define UVS 72
#define VST 516
#define SM_VT 9216
#define SM_TB 25728
#define SM_QHI (SM_TB + 0)
#define SM_QLO (SM_TB + 8192)
#define SM_KHI (SM_TB + 16384)
#define DYN_SMEM (SM_TB + 32768)

__global__ __launch_bounds__(256, 3) void relmat_main(
    const int* __restrict__ ids, float* __restrict__ out)
{
    extern __shared__ char sm8[];
    uint32_t sb = smem_u32(sm8);
    __nv_bfloat16* us_h = (__nv_bfloat16*)(sm8);
    __nv_bfloat16* vs_t = (__nv_bfloat16*)(sm8 + SM_VT);
    float* D_s = (float*)(sm8 + SM_TB);

    int bh = blockIdx.z, b = bh >> 4;
    int l0 = blockIdx.y * 64, m0 = blockIdx.x * 128;
    int tid = threadIdx.x, lane = tid & 31, warp = tid >> 5;
    int warp_m = warp & 1, warp_n = warp >> 1;   // 2x4 warp grid, warp tile 32x32

    // ---- phase 1: all staging via cp.async ----
    {
        const __half* qh = g_qh + ((size_t)bh * LLEN + l0) * 64;
        const __half* ql = g_ql + ((size_t)bh * LLEN + l0) * 64;
        const __half* kh = g_kh + ((size_t)bh * LLEN + m0) * 64;
        const char* ub = (const char*)(g_u + ((size_t)bh * LLEN + l0) * 64);
        const char* vb = (const char*)(g_v + ((size_t)bh * LLEN + m0) * 64);
        // Q hi/lo: 64 rows x 8 16B-chunks each
#pragma unroll
        for (int it = 0; it < 2; it++) {
            int idx = tid + 256 * it;          // [0,512)
            int row = idx >> 3, c8 = idx & 7;
            uint32_t off = SWZ((uint32_t)(row * 128 + c8 * 16));
            cp16(sb + SM_QHI + off, qh + row * 64 + c8 * 8);
            cp16(sb + SM_QLO + off, ql + row * 64 + c8 * 8);
        }
        // K hi: 128 rows x 8 chunks
#pragma unroll
        for (int it = 0; it < 4; it++) {
            int idx = tid + 256 * it;          // [0,1024)
            int row = idx >> 3, c8 = idx & 7;
            cp16(sb + SM_KHI + SWZ((uint32_t)(row * 128 + c8 * 16)),
                 kh + row * 64 + c8 * 8);
        }
        // u: 64 rows x 8 chunks (row-major, stride 144 B -> 8B aligned)
#pragma unroll
        for (int it = 0; it < 2; it++) {
            int idx = tid + 256 * it;          // [0,512)
            int rr = idx >> 3, cc = idx & 7;
            uint32_t d = sb + (uint32_t)(rr * (UVS * 2) + cc * 16);
            cp8(d,     ub + idx * 16);
            cp8(d + 8, ub + idx * 16 + 8);
        }
        // v: 128 rows x 8 chunks -> transposed [rc][m*4+e]
#pragma unroll
        for (int it = 0; it < 4; it++) {
            int idx = tid + 256 * it;          // [0,1024)
            int rr = idx >> 3, cc = idx & 7;
            cp8(sb + SM_VT + (uint32_t)((2 * cc) * (VST * 2) + rr * 8),
                vb + idx * 16);
            cp8(sb + SM_VT + (uint32_t)((2 * cc + 1) * (VST * 2) + rr * 8),
                vb + idx * 16 + 8);
        }
        cp_wait_all();
    }
    __syncthreads();

    // ---- phase 2: GEMM, 2 fp16 passes fused per k-step ----
    float C[2][4][4];
#pragma unroll
    for (int mt = 0; mt < 2; mt++)
#pragma unroll
        for (int nt = 0; nt < 4; nt++)
#pragma unroll
            for (int q = 0; q < 4; q++) C[mt][nt][q] = 0.f;

    int lrowA = warp_m * 32 + (lane & 15);
    int lrowB = warp_n * 32 + (lane & 15);
    int kb = (lane >> 4);

#pragma unroll
    for (int ks = 0; ks < 4; ks++) {
        uint32_t kcol = (uint32_t)((ks * 2 + kb) * 16);
        uint32_t ah[2][4], al[2][4];
#pragma unroll
        for (int mt = 0; mt < 2; mt++) {
            uint32_t aoff = SWZ((uint32_t)((lrowA + mt * 16) * 128) + kcol);
            ldmx4(ah[mt], sb + SM_QHI + aoff);
            ldmx4(al[mt], sb + SM_QLO + aoff);
        }
#pragma unroll
        for (int ntp = 0; ntp < 2; ntp++) {
            uint32_t boff = SWZ((uint32_t)((lrowB + ntp * 16) * 128) + kcol);
            uint32_t bhf[4];
            ldmx4(bhf, sb + SM_KHI + boff);
#pragma unroll
            for (int mt = 0; mt < 2; mt++)
#pragma unroll
                for (int hv = 0; hv < 2; hv++) {
                    int nt = ntp * 2 + hv;
                    mma16816h(C[mt][nt], ah[mt], bhf[hv], bhf[2 + hv]);   // qh*kh
                    mma16816h(C[mt][nt], al[mt], bhf[hv], bhf[2 + hv]);   // ql*kh
                }
        }
    }
    __syncthreads();   // tiles no longer needed; D_s may overwrite

    // ---- phase 3: C fragments -> D_s (slot-swizzled) ----
    {
        int lr = lane >> 2, lc2 = 2 * (lane & 3);
#pragma unroll
        for (int mt = 0; mt < 2; mt++)
#pragma unroll
            for (int nt = 0; nt < 4; nt++)
#pragma unroll
                for (int rh = 0; rh < 2; rh++) {
                    int row = warp_m * 32 + mt * 16 + rh * 8 + lr;
                    int cg = warp_n * 4 + nt;
                    int phys = (cg + row) & 15;
                    *(float2*)&D_s[row * 128 + phys * 8 + lc2] =
                        make_float2(C[mt][nt][rh * 2], C[mt][nt][rh * 2 + 1]);
                }
    }
    __syncthreads();

    // ---- phase 4: row-major epilogue, 8 rows/warp, ids prefetch ----
    const int* idb = ids + ((size_t)b * LLEN + l0) * LLEN + m0;
    float* ob = out + ((size_t)bh * LLEN + l0) * LLEN + m0;
    int cg = lane >> 1, half4 = (lane & 1) * 4;
    const __nv_bfloat16* vt0 = vs_t + lane * 16;

    int4 idbuf[2];
    idbuf[0] = *(const int4*)(idb + (size_t)(warp * 8) * LLEN + lane * 4);
    idbuf[1] = *(const int4*)(idb + (size_t)(warp * 8 + 1) * LLEN + lane * 4);
#pragma unroll
    for (int i = 0; i < 8; i++) {
        int row = warp * 8 + i;
        int4 idp = idbuf[i & 1];
        if (i < 6)
            idbuf[i & 1] = *(const int4*)(idb + (size_t)(row + 2) * LLEN + lane * 4);
        float4 base4 = *(const float4*)&D_s[row * 128 + ((cg + row) & 15) * 8 + half4];
        const __nv_bfloat16* urow = us_h + row * UVS;
        int idv[4] = {idp.x, idp.y, idp.z, idp.w};
        float basev[4] = {base4.x, base4.y, base4.z, base4.w};
        float res[4];
#pragma unroll
        for (int cc = 0; cc < 4; cc++) {
            int id = idv[cc];
            int rc = min(max(id, 0), RREL - 1);
            uint2 up = *(const uint2*)(urow + rc * 4);
            uint2 vp = *(const uint2*)(vt0 + rc * VST + cc * 4);
            __nv_bfloat162 u01 = *(__nv_bfloat162*)&up.x;
            __nv_bfloat162 u23 = *(__nv_bfloat162*)&up.y;
            __nv_bfloat162 v01 = *(__nv_bfloat162*)&vp.x;
            __nv_bfloat162 v23 = *(__nv_bfloat162*)&vp.y;
            __nv_bfloat162 prod = __hmul2(u01, v01);
            prod = __hfma2(u23, v23, prod);
            float low = __low2float(prod) + __high2float(prod);
            res[cc] = ((unsigned)id < RREL) ? (basev[cc] + low) : 0.f;
        }
        *(float4*)(ob + (size_t)row * LLEN + lane * 4) =
            make_float4(res[0], res[1], res[2], res[3]);
    }
}

extern "C" void kernel_launch(void* const* d_in, const int* in_sizes, int n_in,
                              void* d_out, int out_size) {
    const float* Q   = (const float*)d_in[0];
    const float* K   = (const float*)d_in[1];
    const int*   ids = (const int*)d_in[2];
    const float* A1  = (const float*)d_in[3];
    const float* A2  = (const float*)d_in[4];
    float* out = (float*)d_out;

    static int once = 0;
    if (!once) {
        cudaFuncSetAttribute(relmat_main, cudaFuncAttributeMaxDynamicSharedMemorySize, DYN_SMEM);
        once = 1;
    }

    dim3 gpre(2, 16, BB * HH);
    precompute_uv_mma<<<gpre, 128>>>(Q, K, A1, A2);

    dim3 gmain(LLEN / 128, LLEN / 64, BB * HH);
    relmat_main<<<gmain, 256, DYN_SMEM>>>(ids, out);
}